// round 2
// baseline (speedup 1.0000x reference)
#include <cuda_runtime.h>
#include <math.h>

#define Dd 256
#define Bb 32
#define Ff 512
#define Tt 32
#define STR 260   // smem row stride (floats), %4==0 for 8B-aligned f32x2 loads

// ---------------- scratch (device globals; no allocation allowed) -------------
__device__ float  g_pe[Ff * Dd];
__device__ float  g_qw[Ff * Dd];
__device__ float  g_base[Bb * Ff * Dd];
__device__ float  g_sW[Bb * Ff * Dd];
__device__ float2 g_WeP[(Dd / 2) * Dd];
__device__ float2 g_WsP[(Dd / 2) * Dd];
__device__ float  g_WfT[Dd * Dd];
__device__ float  g_WqT[Dd * Dd];
__device__ float  g_WhT[Dd * Dd];
__device__ float  g_wihT[2 * Dd * 4 * Dd];  // [512][1024]
__device__ float  g_whhT[Dd * 4 * Dd];      // [256][1024]
__device__ float  g_wgT[2 * Dd * Dd];       // [512][256]
__device__ float  g_h[Bb * Dd], g_cell[Bb * Dd], g_cp[Bb * Dd], g_hw[Bb * Dd];
__device__ float  g_gates[Bb * 4 * Dd];
__device__ float  g_cpart[16 * Bb * Dd], g_cppart[16 * Bb * Dd];

// ---------------- setup kernels ----------------------------------------------

__global__ void pe_kernel() {
    int idx = blockIdx.x * 256 + threadIdx.x;     // F*D = 131072 -> grid 512
    int pos = idx >> 8;
    int d   = idx & 255;
    float expo = (float)(d & ~1) / (float)Dd;
    float ang  = (float)pos / powf(10000.0f, expo);
    double a = (double)ang;                        // accurate sin/cos of fp32 angle
    g_pe[idx] = (d & 1) ? (float)cos(a) : (float)sin(a);
}

__global__ void transpose_kernel(const float* __restrict__ src, float* __restrict__ dst,
                                 int R, int C) {
    int idx = blockIdx.x * 256 + threadIdx.x;
    if (idx < R * C) {
        int r = idx / C, c = idx % C;
        dst[c * R + r] = src[idx];
    }
}

// pack w[o][d] (256x256) into paired-K layout: dst[k*256+o] = (w[o][2k], w[o][2k+1])
__global__ void pairw_kernel(const float* __restrict__ w, float2* __restrict__ dst) {
    int idx = blockIdx.x * 256 + threadIdx.x;     // 128*256
    int k = idx >> 8, o = idx & 255;
    dst[idx] = make_float2(w[o * Dd + 2 * k], w[o * Dd + 2 * k + 1]);
}

__global__ void zero_kernel(float* p, int n) {
    for (int i = blockIdx.x * blockDim.x + threadIdx.x; i < n; i += gridDim.x * blockDim.x)
        p[i] = 0.0f;
}

// C[row][o] = sum_d A[row][d]*WT[d][o] (+ add[(row&mask)][o]); 32 rows / block
__global__ void rowgemm_kernel(const float* __restrict__ A, const float* __restrict__ WT,
                               const float* __restrict__ add, int mask,
                               float* __restrict__ C) {
    __shared__ float As[32 * Dd];
    int f0 = blockIdx.x * 32;
    int o  = threadIdx.x;
    for (int r = 0; r < 32; r++)
        As[r * Dd + o] = A[(size_t)(f0 + r) * Dd + o];
    __syncthreads();
    float acc[32];
#pragma unroll
    for (int r = 0; r < 32; r++) acc[r] = 0.0f;
    for (int d = 0; d < Dd; d++) {
        float w = WT[d * Dd + o];
#pragma unroll
        for (int r = 0; r < 32; r++) acc[r] += As[r * Dd + d] * w;
    }
    for (int r = 0; r < 32; r++) {
        int row = f0 + r;
        float v = acc[r];
        if (add) v += add[(size_t)(row & mask) * Dd + o];
        C[(size_t)row * Dd + o] = v;
    }
}

// ---------------- per-step kernels -------------------------------------------

__device__ __forceinline__ float sigm(float x) { return 1.0f / (1.0f + expf(-x)); }

// gates[b][g*256+tid] = xin @ w_ih^T + h @ w_hh^T ; grid (B, 4)
__global__ void lstm_gates_kernel(const int* __restrict__ ids,
                                  const float* __restrict__ emb, int t) {
    int b = blockIdx.x, g = blockIdx.y, tid = threadIdx.x;
    __shared__ float buf[768];
    int id = ids[b * Tt + t];
    buf[tid]       = emb[id * Dd + tid];
    buf[256 + tid] = g_cp[b * Dd + tid];
    buf[512 + tid] = g_h[b * Dd + tid];
    __syncthreads();
    int gcol = g * 256 + tid;
    float acc = 0.0f;
    for (int j = 0; j < 512; j++) acc += buf[j] * g_wihT[j * 1024 + gcol];
    for (int j = 0; j < 256; j++) acc += buf[512 + j] * g_whhT[j * 1024 + gcol];
    g_gates[b * 1024 + gcol] = acc;
}

// cell/h update (torch gate order i,f,g,o) + hw = h @ w_h^T ; grid B
__global__ void lstm_update_kernel() {
    int b = blockIdx.x, tid = threadIdx.x;
    __shared__ float hs[256];
    const float* gb = g_gates + b * 1024;
    float gi = gb[tid], gf = gb[256 + tid], gg = gb[512 + tid], go = gb[768 + tid];
    float c  = sigm(gf) * g_cell[b * Dd + tid] + sigm(gi) * tanhf(gg);
    float hn = sigm(go) * tanhf(c);
    g_cell[b * Dd + tid] = c;
    g_h[b * Dd + tid]    = hn;
    hs[tid] = hn;
    __syncthreads();
    float acc = 0.0f;
    for (int d = 0; d < Dd; d++) acc += hs[d] * g_WhT[d * Dd + tid];
    g_hw[b * Dd + tid] = acc;
}

// Fused attention step: tanh -> GEMM(We^T) -> softmax(D) -> c/cp partials
//                       -> GEMM(Ws^T) accumulated into sW.  grid = B*F/32 = 512.
__global__ void __launch_bounds__(256) attn_kernel(const float* __restrict__ f) {
    __shared__ float S[32 * STR];
    int bid = blockIdx.x;
    int b = bid >> 4, p = bid & 15, f0 = p * 32;
    int o = threadIdx.x;
    size_t rb = ((size_t)b * Ff + f0) * Dd;

    float hwv = g_hw[b * Dd + o];
#pragma unroll 4
    for (int r = 0; r < 32; r++)
        S[r * STR + o] = tanhf(hwv + g_base[rb + r * Dd + o] + g_sW[rb + r * Dd + o]);
    __syncthreads();

    // ---- GEMM 1: E = X @ We^T  (packed f32x2 over K) ----
    unsigned long long acc[32];
#pragma unroll
    for (int r = 0; r < 32; r++) acc[r] = 0ULL;
    {
        const unsigned long long* WeP = (const unsigned long long*)g_WeP;
        for (int k = 0; k < 128; k++) {
            unsigned long long w = WeP[k * Dd + o];
#pragma unroll
            for (int r = 0; r < 32; r++) {
                unsigned long long x = *(const unsigned long long*)(S + r * STR + 2 * k);
                asm("fma.rn.f32x2 %0, %1, %2, %0;" : "+l"(acc[r]) : "l"(x), "l"(w));
            }
        }
    }
    __syncthreads();
#pragma unroll
    for (int r = 0; r < 32; r++)
        S[r * STR + o] = __uint_as_float((unsigned)acc[r]) +
                         __uint_as_float((unsigned)(acc[r] >> 32));
    __syncthreads();

    // ---- softmax over the 256 columns of each row; warp w owns rows 4w..4w+3 ----
    int wi = o >> 5, lane = o & 31;
    for (int rr = 0; rr < 4; rr++) {
        int r = wi * 4 + rr;
        float v[8];
        float m = -1e30f;
#pragma unroll
        for (int k2 = 0; k2 < 8; k2++) { v[k2] = S[r * STR + lane + 32 * k2]; m = fmaxf(m, v[k2]); }
#pragma unroll
        for (int off = 16; off >= 1; off >>= 1) m = fmaxf(m, __shfl_xor_sync(0xffffffffu, m, off));
        float s = 0.0f;
#pragma unroll
        for (int k2 = 0; k2 < 8; k2++) { v[k2] = expf(v[k2] - m); s += v[k2]; }
#pragma unroll
        for (int off = 16; off >= 1; off >>= 1) s += __shfl_xor_sync(0xffffffffu, s, off);
        float inv = 1.0f / s;
#pragma unroll
        for (int k2 = 0; k2 < 8; k2++) S[r * STR + lane + 32 * k2] = v[k2] * inv;
    }
    __syncthreads();

    // ---- c / cp partial reductions over this f-tile ----
    float cacc = 0.0f, cpacc = 0.0f;
#pragma unroll 4
    for (int r = 0; r < 32; r++) {
        float a  = S[r * STR + o];
        float fv = f[rb + r * Dd + o];
        cacc  += a * fv;
        cpacc += a * (fv + g_pe[(f0 + r) * Dd + o]);
    }
    g_cpart[(p * Bb + b) * Dd + o]  = cacc;
    g_cppart[(p * Bb + b) * Dd + o] = cpacc;

    // ---- GEMM 2: sW += alpha @ Ws^T ----
#pragma unroll
    for (int r = 0; r < 32; r++) acc[r] = 0ULL;
    {
        const unsigned long long* WsP = (const unsigned long long*)g_WsP;
        for (int k = 0; k < 128; k++) {
            unsigned long long w = WsP[k * Dd + o];
#pragma unroll
            for (int r = 0; r < 32; r++) {
                unsigned long long x = *(const unsigned long long*)(S + r * STR + 2 * k);
                asm("fma.rn.f32x2 %0, %1, %2, %0;" : "+l"(acc[r]) : "l"(x), "l"(w));
            }
        }
    }
    for (int r = 0; r < 32; r++)
        g_sW[rb + r * Dd + o] += __uint_as_float((unsigned)acc[r]) +
                                 __uint_as_float((unsigned)(acc[r] >> 32));
}

// reduce c/cp partials, update cp state, pred = [c,h] @ w_g^T ; grid B
__global__ void pred_kernel(float* __restrict__ out, int t) {
    int b = blockIdx.x, tid = threadIdx.x;
    __shared__ float ch[512];
    float cs = 0.0f, cps = 0.0f;
    for (int p = 0; p < 16; p++) {
        cs  += g_cpart[(p * Bb + b) * Dd + tid];
        cps += g_cppart[(p * Bb + b) * Dd + tid];
    }
    g_cp[b * Dd + tid] = cps;
    ch[tid]       = cs;
    ch[256 + tid] = g_h[b * Dd + tid];
    __syncthreads();
    float acc = 0.0f;
    for (int j = 0; j < 512; j++) acc += ch[j] * g_wgT[j * Dd + tid];
    out[((size_t)b * Tt + t) * Dd + tid] = acc;
}

// ---------------- launch ------------------------------------------------------

extern "C" void kernel_launch(void* const* d_in, const int* in_sizes, int n_in,
                              void* d_out, int out_size) {
    (void)in_sizes; (void)n_in; (void)out_size;
    const float* f    = (const float*)d_in[0];
    const int*   ids  = (const int*)d_in[1];
    const float* emb  = (const float*)d_in[2];
    const float* w_e  = (const float*)d_in[3];
    const float* w_h  = (const float*)d_in[4];
    const float* w_f  = (const float*)d_in[5];
    const float* w_q  = (const float*)d_in[6];
    const float* w_s  = (const float*)d_in[7];
    const float* w_g  = (const float*)d_in[8];
    const float* w_ih = (const float*)d_in[9];
    const float* w_hh = (const float*)d_in[10];
    float* out = (float*)d_out;

    float *pWfT, *pWqT, *pWhT, *pwihT, *pwhhT, *pwgT, *psW, *ph, *pcell, *pcp, *ppe, *pqw, *pbase;
    float2 *pWeP, *pWsP;
    cudaGetSymbolAddress((void**)&pWfT,  g_WfT);
    cudaGetSymbolAddress((void**)&pWqT,  g_WqT);
    cudaGetSymbolAddress((void**)&pWhT,  g_WhT);
    cudaGetSymbolAddress((void**)&pwihT, g_wihT);
    cudaGetSymbolAddress((void**)&pwhhT, g_whhT);
    cudaGetSymbolAddress((void**)&pwgT,  g_wgT);
    cudaGetSymbolAddress((void**)&psW,   g_sW);
    cudaGetSymbolAddress((void**)&ph,    g_h);
    cudaGetSymbolAddress((void**)&pcell, g_cell);
    cudaGetSymbolAddress((void**)&pcp,   g_cp);
    cudaGetSymbolAddress((void**)&ppe,   g_pe);
    cudaGetSymbolAddress((void**)&pqw,   g_qw);
    cudaGetSymbolAddress((void**)&pbase, g_base);
    cudaGetSymbolAddress((void**)&pWeP,  g_WeP);
    cudaGetSymbolAddress((void**)&pWsP,  g_WsP);

    // setup
    pe_kernel<<<512, 256>>>();
    transpose_kernel<<<(256 * 256 + 255) / 256, 256>>>(w_f, pWfT, 256, 256);
    transpose_kernel<<<(256 * 256 + 255) / 256, 256>>>(w_q, pWqT, 256, 256);
    transpose_kernel<<<(256 * 256 + 255) / 256, 256>>>(w_h, pWhT, 256, 256);
    transpose_kernel<<<(1024 * 512 + 255) / 256, 256>>>(w_ih, pwihT, 1024, 512);
    transpose_kernel<<<(1024 * 256 + 255) / 256, 256>>>(w_hh, pwhhT, 1024, 256);
    transpose_kernel<<<(256 * 512 + 255) / 256, 256>>>(w_g, pwgT, 256, 512);
    pairw_kernel<<<128, 256>>>(w_e, pWeP);
    pairw_kernel<<<128, 256>>>(w_s, pWsP);
    zero_kernel<<<2048, 256>>>(psW, Bb * Ff * Dd);
    zero_kernel<<<32, 256>>>(ph,    Bb * Dd);
    zero_kernel<<<32, 256>>>(pcell, Bb * Dd);
    zero_kernel<<<32, 256>>>(pcp,   Bb * Dd);
    rowgemm_kernel<<<16, 256>>>(ppe, pWqT, nullptr, 0, pqw);           // qw = pe @ w_q^T
    rowgemm_kernel<<<512, 256>>>(f, pWfT, pqw, Ff - 1, pbase);         // base = f@w_f^T + qw

    // decode loop
    for (int t = 0; t < Tt; t++) {
        lstm_gates_kernel<<<dim3(32, 4), 256>>>(ids, emb, t);
        lstm_update_kernel<<<32, 256>>>();
        attn_kernel<<<512, 256>>>(f);
        pred_kernel<<<32, 256>>>(out, t);
    }
}

// round 3
// speedup vs baseline: 1.8411x; 1.8411x over previous
#include <cuda_runtime.h>
#include <math.h>

#define Dd 256
#define Bb 32
#define Ff 512
#define Tt 32
#define STR 260   // smem row stride (floats), %4==0 for 8B-aligned f32x2 loads

// ---------------- scratch (device globals; no allocation allowed) -------------
__device__ float  g_pe[Ff * Dd];
__device__ float  g_qw[Ff * Dd];
__device__ float  g_base[Bb * Ff * Dd];
__device__ float  g_sW[Bb * Ff * Dd];
__device__ float2 g_WeP[(Dd / 2) * Dd];
__device__ float2 g_WsP[(Dd / 2) * Dd];
__device__ float  g_WfT[Dd * Dd];
__device__ float  g_WqT[Dd * Dd];
__device__ float  g_WhT[Dd * Dd];
__device__ float  g_wcomb[768 * 1024];      // rows 0-511: w_ih^T, rows 512-767: w_hh^T
__device__ float  g_wgT[2 * Dd * Dd];       // [512][256]
__device__ float  g_h[Bb * Dd], g_cell[Bb * Dd], g_cp[Bb * Dd], g_hw[Bb * Dd];
__device__ float  g_cpart[16 * Bb * Dd], g_cppart[16 * Bb * Dd];

__device__ __forceinline__ float sigm(float x) { return 1.0f / (1.0f + expf(-x)); }

// ---------------- setup (fused into 4 launches for ncu -s 5 alignment) --------

// block ranges: [0,512) pe | [512,768) w_f^T | [768,1024) w_q^T | [1024,1280) w_h^T
// [1280,3328) w_ih^T->wcomb | [3328,4352) w_hh^T->wcomb+512 rows | [4352,4864) w_g^T
// [4864,4992) pairw w_e | [4992,5120) pairw w_s
__global__ void setup_a(const float* __restrict__ w_f, const float* __restrict__ w_q,
                        const float* __restrict__ w_h, const float* __restrict__ w_ih,
                        const float* __restrict__ w_hh, const float* __restrict__ w_g,
                        const float* __restrict__ w_e, const float* __restrict__ w_s) {
    int bb = blockIdx.x, tid = threadIdx.x;
    if (bb < 512) {                                   // position encoding
        int idx = bb * 256 + tid;
        int pos = idx >> 8, d = idx & 255;
        float expo = (float)(d & ~1) / (float)Dd;
        float ang  = (float)pos / powf(10000.0f, expo);
        double a = (double)ang;
        g_pe[idx] = (d & 1) ? (float)cos(a) : (float)sin(a);
    } else if (bb < 1024) {                           // 256x256 transposes (w_f, w_q)
        int which = (bb - 512) >> 8;
        int idx = ((bb - 512) & 255) * 256 + tid;
        int r = idx >> 8, c = idx & 255;
        const float* src = which ? w_q : w_f;
        float* dst = which ? g_WqT : g_WfT;
        dst[c * 256 + r] = src[idx];
    } else if (bb < 1280) {                           // w_h^T
        int idx = (bb - 1024) * 256 + tid;
        int r = idx >> 8, c = idx & 255;
        g_WhT[c * 256 + r] = w_h[idx];
    } else if (bb < 3328) {                           // w_ih [1024][512] -> wcomb rows 0-511
        int idx = (bb - 1280) * 256 + tid;
        int r = idx / 512, c = idx % 512;
        g_wcomb[c * 1024 + r] = w_ih[idx];
    } else if (bb < 4352) {                           // w_hh [1024][256] -> wcomb rows 512-767
        int idx = (bb - 3328) * 256 + tid;
        int r = idx >> 8, c = idx & 255;
        g_wcomb[(512 + c) * 1024 + r] = w_hh[idx];
    } else if (bb < 4864) {                           // w_g [256][512] -> wgT [512][256]
        int idx = (bb - 4352) * 256 + tid;
        int r = idx / 512, c = idx % 512;
        g_wgT[c * 256 + r] = w_g[idx];
    } else if (bb < 4992) {                           // pair-pack w_e
        int idx = (bb - 4864) * 256 + tid;
        int k = idx >> 8, o = idx & 255;
        g_WeP[idx] = make_float2(w_e[o * Dd + 2 * k], w_e[o * Dd + 2 * k + 1]);
    } else {                                          // pair-pack w_s
        int idx = (bb - 4992) * 256 + tid;
        int k = idx >> 8, o = idx & 255;
        g_WsP[idx] = make_float2(w_s[o * Dd + 2 * k], w_s[o * Dd + 2 * k + 1]);
    }
}

__global__ void setup_zero() {
    int n = Bb * Ff * Dd;
    for (int i = blockIdx.x * blockDim.x + threadIdx.x; i < n; i += gridDim.x * blockDim.x) {
        g_sW[i] = 0.0f;
        if (i < Bb * Dd) { g_h[i] = 0.0f; g_cell[i] = 0.0f; g_cp[i] = 0.0f; }
    }
}

// C[row][o] = sum_d A[row][d]*WT[d][o] (+ add[(row&mask)][o]); 32 rows / block
__global__ void rowgemm_kernel(const float* __restrict__ A, const float* __restrict__ WT,
                               const float* __restrict__ add, int mask,
                               float* __restrict__ C) {
    __shared__ float As[32 * Dd];
    int f0 = blockIdx.x * 32;
    int o  = threadIdx.x;
    for (int r = 0; r < 32; r++)
        As[r * Dd + o] = A[(size_t)(f0 + r) * Dd + o];
    __syncthreads();
    float acc[32];
#pragma unroll
    for (int r = 0; r < 32; r++) acc[r] = 0.0f;
    for (int d = 0; d < Dd; d++) {
        float w = WT[d * Dd + o];
#pragma unroll
        for (int r = 0; r < 32; r++) acc[r] += As[r * Dd + d] * w;
    }
    for (int r = 0; r < 32; r++) {
        int row = f0 + r;
        float v = acc[r];
        if (add) v += add[(size_t)(row & mask) * Dd + o];
        C[(size_t)row * Dd + o] = v;
    }
}

// ---------------- per-step kernels -------------------------------------------

// Fused LSTM step: gates (1024 outputs, 768-dot each) + cell/h update + hw = h@Wh^T
// grid = B, block = 1024
__global__ void lstm_step_kernel(const int* __restrict__ ids,
                                 const float* __restrict__ emb, int t) {
    int b = blockIdx.x, tid = threadIdx.x;
    __shared__ float buf[768];
    __shared__ float gsh[1024];
    if (tid < 256)      buf[tid] = emb[ids[b * Tt + t] * Dd + tid];
    else if (tid < 512) buf[tid] = g_cp[b * Dd + (tid - 256)];
    else if (tid < 768) buf[tid] = g_h[b * Dd + (tid - 512)];
    __syncthreads();
    float acc = 0.0f;
#pragma unroll 4
    for (int j = 0; j < 768; j++) acc += buf[j] * g_wcomb[j * 1024 + tid];
    gsh[tid] = acc;
    __syncthreads();
    if (tid < 256) {
        float gi = gsh[tid], gf = gsh[256 + tid], gg = gsh[512 + tid], go = gsh[768 + tid];
        float c  = sigm(gf) * g_cell[b * Dd + tid] + sigm(gi) * tanhf(gg);
        float hn = sigm(go) * tanhf(c);
        g_cell[b * Dd + tid] = c;
        g_h[b * Dd + tid]    = hn;
        buf[tid] = hn;
    }
    __syncthreads();
    if (tid < 256) {
        float a = 0.0f;
#pragma unroll 4
        for (int d = 0; d < Dd; d++) a += buf[d] * g_WhT[d * Dd + tid];
        g_hw[b * Dd + tid] = a;
    }
}

// Fused attention step: tanh -> GEMM(We^T) -> softmax(D) -> c/cp partials
//                       -> GEMM(Ws^T) accumulated into sW.  grid = B*F/32 = 512.
// GEMM mapping: thread tid -> 8 rows (rg = tid>>6) x 4 outputs (o0 = tid&63, +64j).
__global__ void __launch_bounds__(256, 2) attn_kernel(const float* __restrict__ f) {
    __shared__ float S[32 * STR];
    int bid = blockIdx.x;
    int b = bid >> 4, p = bid & 15, f0 = p * 32;
    int tid = threadIdx.x;
    size_t rb = ((size_t)b * Ff + f0) * Dd;

    // phase 1: X = tanh(hw + base + sW); thread tid owns column tid
    {
        float hwv = g_hw[b * Dd + tid];
#pragma unroll 4
        for (int r = 0; r < 32; r++)
            S[r * STR + tid] = tanhf(hwv + g_base[rb + r * Dd + tid] + g_sW[rb + r * Dd + tid]);
    }
    __syncthreads();

    int o0 = tid & 63;
    int r0 = (tid >> 6) * 8;

    // ---- GEMM 1: E = X @ We^T  (8r x 4o register blocking, packed f32x2) ----
    unsigned long long acc[32];
#pragma unroll
    for (int i = 0; i < 32; i++) acc[i] = 0ULL;
    {
        const unsigned long long* WeP = (const unsigned long long*)g_WeP;
        for (int k = 0; k < 128; k++) {
            unsigned long long w0 = WeP[k * Dd + o0];
            unsigned long long w1 = WeP[k * Dd + o0 + 64];
            unsigned long long w2 = WeP[k * Dd + o0 + 128];
            unsigned long long w3 = WeP[k * Dd + o0 + 192];
#pragma unroll
            for (int i = 0; i < 8; i++) {
                unsigned long long x = *(const unsigned long long*)(S + (r0 + i) * STR + 2 * k);
                asm("fma.rn.f32x2 %0, %1, %2, %0;" : "+l"(acc[i * 4 + 0]) : "l"(x), "l"(w0));
                asm("fma.rn.f32x2 %0, %1, %2, %0;" : "+l"(acc[i * 4 + 1]) : "l"(x), "l"(w1));
                asm("fma.rn.f32x2 %0, %1, %2, %0;" : "+l"(acc[i * 4 + 2]) : "l"(x), "l"(w2));
                asm("fma.rn.f32x2 %0, %1, %2, %0;" : "+l"(acc[i * 4 + 3]) : "l"(x), "l"(w3));
            }
        }
    }
    __syncthreads();
#pragma unroll
    for (int i = 0; i < 8; i++)
#pragma unroll
        for (int j = 0; j < 4; j++) {
            unsigned long long a = acc[i * 4 + j];
            S[(r0 + i) * STR + o0 + 64 * j] =
                __uint_as_float((unsigned)a) + __uint_as_float((unsigned)(a >> 32));
        }
    __syncthreads();

    // ---- softmax over the 256 columns of each row; warp w owns rows 4w..4w+3 ----
    {
        int wi = tid >> 5, lane = tid & 31;
        for (int rr = 0; rr < 4; rr++) {
            int r = wi * 4 + rr;
            float v[8];
            float m = -1e30f;
#pragma unroll
            for (int k2 = 0; k2 < 8; k2++) { v[k2] = S[r * STR + lane + 32 * k2]; m = fmaxf(m, v[k2]); }
#pragma unroll
            for (int off = 16; off >= 1; off >>= 1) m = fmaxf(m, __shfl_xor_sync(0xffffffffu, m, off));
            float s = 0.0f;
#pragma unroll
            for (int k2 = 0; k2 < 8; k2++) { v[k2] = __expf(v[k2] - m); s += v[k2]; }
#pragma unroll
            for (int off = 16; off >= 1; off >>= 1) s += __shfl_xor_sync(0xffffffffu, s, off);
            float inv = 1.0f / s;
#pragma unroll
            for (int k2 = 0; k2 < 8; k2++) S[r * STR + lane + 32 * k2] = v[k2] * inv;
        }
    }
    __syncthreads();

    // ---- c / cp partial reductions over this f-tile (thread tid = column tid) ----
    {
        float cacc = 0.0f, cpacc = 0.0f;
#pragma unroll 4
        for (int r = 0; r < 32; r++) {
            float a  = S[r * STR + tid];
            float fv = f[rb + r * Dd + tid];
            cacc  += a * fv;
            cpacc += a * (fv + g_pe[(f0 + r) * Dd + tid]);
        }
        g_cpart[(p * Bb + b) * Dd + tid]  = cacc;
        g_cppart[(p * Bb + b) * Dd + tid] = cpacc;
    }

    // ---- GEMM 2: sW += alpha @ Ws^T ----
#pragma unroll
    for (int i = 0; i < 32; i++) acc[i] = 0ULL;
    {
        const unsigned long long* WsP = (const unsigned long long*)g_WsP;
        for (int k = 0; k < 128; k++) {
            unsigned long long w0 = WsP[k * Dd + o0];
            unsigned long long w1 = WsP[k * Dd + o0 + 64];
            unsigned long long w2 = WsP[k * Dd + o0 + 128];
            unsigned long long w3 = WsP[k * Dd + o0 + 192];
#pragma unroll
            for (int i = 0; i < 8; i++) {
                unsigned long long x = *(const unsigned long long*)(S + (r0 + i) * STR + 2 * k);
                asm("fma.rn.f32x2 %0, %1, %2, %0;" : "+l"(acc[i * 4 + 0]) : "l"(x), "l"(w0));
                asm("fma.rn.f32x2 %0, %1, %2, %0;" : "+l"(acc[i * 4 + 1]) : "l"(x), "l"(w1));
                asm("fma.rn.f32x2 %0, %1, %2, %0;" : "+l"(acc[i * 4 + 2]) : "l"(x), "l"(w2));
                asm("fma.rn.f32x2 %0, %1, %2, %0;" : "+l"(acc[i * 4 + 3]) : "l"(x), "l"(w3));
            }
        }
    }
#pragma unroll
    for (int i = 0; i < 8; i++)
#pragma unroll
        for (int j = 0; j < 4; j++) {
            unsigned long long a = acc[i * 4 + j];
            size_t gi = rb + (size_t)(r0 + i) * Dd + o0 + 64 * j;
            g_sW[gi] += __uint_as_float((unsigned)a) + __uint_as_float((unsigned)(a >> 32));
        }
}

// reduce c/cp partials, update cp state, pred = [c,h] @ w_g^T ; grid B
__global__ void pred_kernel(float* __restrict__ out, int t) {
    int b = blockIdx.x, tid = threadIdx.x;
    __shared__ float ch[512];
    float cs = 0.0f, cps = 0.0f;
#pragma unroll
    for (int p = 0; p < 16; p++) {
        cs  += g_cpart[(p * Bb + b) * Dd + tid];
        cps += g_cppart[(p * Bb + b) * Dd + tid];
    }
    g_cp[b * Dd + tid] = cps;
    ch[tid]       = cs;
    ch[256 + tid] = g_h[b * Dd + tid];
    __syncthreads();
    float acc = 0.0f;
#pragma unroll 4
    for (int j = 0; j < 512; j++) acc += ch[j] * g_wgT[j * Dd + tid];
    out[((size_t)b * Tt + t) * Dd + tid] = acc;
}

// ---------------- launch ------------------------------------------------------

extern "C" void kernel_launch(void* const* d_in, const int* in_sizes, int n_in,
                              void* d_out, int out_size) {
    (void)in_sizes; (void)n_in; (void)out_size;
    const float* f    = (const float*)d_in[0];
    const int*   ids  = (const int*)d_in[1];
    const float* emb  = (const float*)d_in[2];
    const float* w_e  = (const float*)d_in[3];
    const float* w_h  = (const float*)d_in[4];
    const float* w_f  = (const float*)d_in[5];
    const float* w_q  = (const float*)d_in[6];
    const float* w_s  = (const float*)d_in[7];
    const float* w_g  = (const float*)d_in[8];
    const float* w_ih = (const float*)d_in[9];
    const float* w_hh = (const float*)d_in[10];
    float* out = (float*)d_out;

    float *pWfT, *pWqT, *ppe, *pqw, *pbase;
    cudaGetSymbolAddress((void**)&pWfT,  g_WfT);
    cudaGetSymbolAddress((void**)&pWqT,  g_WqT);
    cudaGetSymbolAddress((void**)&ppe,   g_pe);
    cudaGetSymbolAddress((void**)&pqw,   g_qw);
    cudaGetSymbolAddress((void**)&pbase, g_base);

    // setup: exactly 4 launches so launch index 5 (ncu -s 5 -c 1) = attn_kernel(t=0)
    setup_a<<<5120, 256>>>(w_f, w_q, w_h, w_ih, w_hh, w_g, w_e, w_s);       // 0
    setup_zero<<<2048, 256>>>();                                            // 1
    rowgemm_kernel<<<16, 256>>>(ppe, pWqT, nullptr, 0, pqw);                // 2
    rowgemm_kernel<<<512, 256>>>(f, pWfT, pqw, Ff - 1, pbase);              // 3

    // decode loop: 3 launches per step
    for (int t = 0; t < Tt; t++) {
        lstm_step_kernel<<<32, 1024>>>(ids, emb, t);                        // 4 (t=0)
        attn_kernel<<<512, 256>>>(f);                                       // 5 (t=0) <- profiled
        pred_kernel<<<32, 256>>>(out, t);
    }
}

// round 4
// speedup vs baseline: 2.2260x; 1.2091x over previous
#include <cuda_runtime.h>
#include <math.h>

#define Dd 256
#define Bb 32
#define Ff 512
#define Tt 32
#define STR 260   // smem row stride (floats); 260*4=1040 bytes = 65*16 -> 16B-aligned rows

typedef unsigned long long ull;

// ---------------- scratch (device globals; no allocation allowed) -------------
__device__ float g_pe[Ff * Dd];
__device__ float g_base[Bb * Ff * Dd];
__device__ float g_sW[Bb * Ff * Dd];
__device__ ull   g_WeP[128 * 256];      // [kpair][o] packed (w[o][2k], w[o][2k+1])
__device__ ull   g_WsP[128 * 256];
__device__ ull   g_WfP[128 * 256];
__device__ ull   g_WqP[128 * 256];
__device__ ull   g_WhP[128 * 256];
__device__ ull   g_wcombP[384 * 1024];  // [jp][gcol]; jp<256 from w_ih, else w_hh
__device__ ull   g_WgP[256 * 256];      // [jp][o]
__device__ float g_h[Bb * Dd], g_cell[Bb * Dd], g_cp[Bb * Dd], g_hw[Bb * Dd];
__device__ float g_cpart[16 * Bb * Dd], g_cppart[16 * Bb * Dd];

__device__ __forceinline__ float sigm(float x) { return 1.0f / (1.0f + expf(-x)); }
__device__ __forceinline__ ull pack2(float a, float b) {
    ull r; asm("mov.b64 %0, {%1, %2};" : "=l"(r) : "f"(a), "f"(b)); return r;
}
__device__ __forceinline__ float red2(ull a) {
    return __uint_as_float((unsigned)a) + __uint_as_float((unsigned)(a >> 32));
}

// ---------------- mega-setup: one launch --------------------------------------
// [0,512) pe | [512,640) WhP | [640,2176) wcombP | [2176,2432) WgP
// [2432,2560) WeP | [2560,2688) WsP | [2688,2816) WfP | [2816,2944) WqP
// [2944,4992) zero sW | [4992,5088) zero h/cell/cp
__global__ void setup_a(const float* __restrict__ w_f, const float* __restrict__ w_q,
                        const float* __restrict__ w_h, const float* __restrict__ w_ih,
                        const float* __restrict__ w_hh, const float* __restrict__ w_g,
                        const float* __restrict__ w_e, const float* __restrict__ w_s) {
    int bb = blockIdx.x, tid = threadIdx.x;
    if (bb < 512) {
        int idx = bb * 256 + tid;
        int pos = idx >> 8, d = idx & 255;
        float expo = (float)(d & ~1) / (float)Dd;
        float ang  = (float)pos / powf(10000.0f, expo);
        double a = (double)ang;
        g_pe[idx] = (d & 1) ? (float)cos(a) : (float)sin(a);
    } else if (bb < 640) {
        int idx = (bb - 512) * 256 + tid;
        int k = idx >> 8, o = idx & 255;
        g_WhP[idx] = pack2(w_h[o * 256 + 2 * k], w_h[o * 256 + 2 * k + 1]);
    } else if (bb < 2176) {
        int idx = (bb - 640) * 256 + tid;       // 393216 cells
        int jp = idx >> 10, gcol = idx & 1023;
        float a, b;
        if (jp < 256) { a = w_ih[gcol * 512 + 2 * jp];        b = w_ih[gcol * 512 + 2 * jp + 1]; }
        else { int j2 = jp - 256; a = w_hh[gcol * 256 + 2 * j2]; b = w_hh[gcol * 256 + 2 * j2 + 1]; }
        g_wcombP[idx] = pack2(a, b);
    } else if (bb < 2432) {
        int idx = (bb - 2176) * 256 + tid;      // 65536
        int jp = idx >> 8, o = idx & 255;
        g_WgP[idx] = pack2(w_g[o * 512 + 2 * jp], w_g[o * 512 + 2 * jp + 1]);
    } else if (bb < 2560) {
        int idx = (bb - 2432) * 256 + tid;
        int k = idx >> 8, o = idx & 255;
        g_WeP[idx] = pack2(w_e[o * 256 + 2 * k], w_e[o * 256 + 2 * k + 1]);
    } else if (bb < 2688) {
        int idx = (bb - 2560) * 256 + tid;
        int k = idx >> 8, o = idx & 255;
        g_WsP[idx] = pack2(w_s[o * 256 + 2 * k], w_s[o * 256 + 2 * k + 1]);
    } else if (bb < 2816) {
        int idx = (bb - 2688) * 256 + tid;
        int k = idx >> 8, o = idx & 255;
        g_WfP[idx] = pack2(w_f[o * 256 + 2 * k], w_f[o * 256 + 2 * k + 1]);
    } else if (bb < 2944) {
        int idx = (bb - 2816) * 256 + tid;
        int k = idx >> 8, o = idx & 255;
        g_WqP[idx] = pack2(w_q[o * 256 + 2 * k], w_q[o * 256 + 2 * k + 1]);
    } else if (bb < 4992) {
        int base = (bb - 2944) * 2048;
#pragma unroll
        for (int it = 0; it < 8; it++) g_sW[base + it * 256 + tid] = 0.0f;
    } else {
        int idx = (bb - 4992) * 256 + tid;      // 24576
        if (idx < 8192) g_h[idx] = 0.0f;
        else if (idx < 16384) g_cell[idx - 8192] = 0.0f;
        else g_cp[idx - 16384] = 0.0f;
    }
}

// ---------------- shared staged-GEMM core -------------------------------------
// acc[i*4+j] (packed f32x2) += S[32 x 256] @ W^T columns {o0+64j}, rows r0..r0+7.
// Weights double-buffered in smem; inner loop = LDS + FFMA2 only.
__device__ __forceinline__ void gemm_tile(const float* S, const ull* __restrict__ Wg,
                                          ulonglong2* wb, ull acc[32], int tid) {
    int o0 = tid & 63, r0 = (tid >> 6) * 8;
    ull pw[8];
#pragma unroll
    for (int c = 0; c < 4; c++) {
        pw[2 * c]     = Wg[(2 * c) * 256 + tid];
        pw[2 * c + 1] = Wg[(2 * c + 1) * 256 + tid];
    }
#pragma unroll
    for (int c = 0; c < 4; c++)
        wb[c * 256 + tid] = make_ulonglong2(pw[2 * c], pw[2 * c + 1]);
    __syncthreads();
    for (int ch = 0; ch < 16; ch++) {
        int cur = ch & 1;
        if (ch < 15) {
            const ull* src = Wg + (ch + 1) * 8 * 256;
#pragma unroll
            for (int c = 0; c < 4; c++) {
                pw[2 * c]     = src[(2 * c) * 256 + tid];
                pw[2 * c + 1] = src[(2 * c + 1) * 256 + tid];
            }
        }
        const ulonglong2* wc = wb + cur * 1024;
#pragma unroll
        for (int d = 0; d < 4; d++) {
            ulonglong2 w0 = wc[d * 256 + o0];
            ulonglong2 w1 = wc[d * 256 + o0 + 64];
            ulonglong2 w2 = wc[d * 256 + o0 + 128];
            ulonglong2 w3 = wc[d * 256 + o0 + 192];
            const float* Sp = S + r0 * STR + ch * 16 + d * 4;
#pragma unroll
            for (int i = 0; i < 8; i++) {
                ulonglong2 x = *(const ulonglong2*)(Sp + i * STR);
                asm("fma.rn.f32x2 %0,%1,%2,%0;" : "+l"(acc[i*4+0]) : "l"(x.x), "l"(w0.x));
                asm("fma.rn.f32x2 %0,%1,%2,%0;" : "+l"(acc[i*4+0]) : "l"(x.y), "l"(w0.y));
                asm("fma.rn.f32x2 %0,%1,%2,%0;" : "+l"(acc[i*4+1]) : "l"(x.x), "l"(w1.x));
                asm("fma.rn.f32x2 %0,%1,%2,%0;" : "+l"(acc[i*4+1]) : "l"(x.y), "l"(w1.y));
                asm("fma.rn.f32x2 %0,%1,%2,%0;" : "+l"(acc[i*4+2]) : "l"(x.x), "l"(w2.x));
                asm("fma.rn.f32x2 %0,%1,%2,%0;" : "+l"(acc[i*4+2]) : "l"(x.y), "l"(w2.y));
                asm("fma.rn.f32x2 %0,%1,%2,%0;" : "+l"(acc[i*4+3]) : "l"(x.x), "l"(w3.x));
                asm("fma.rn.f32x2 %0,%1,%2,%0;" : "+l"(acc[i*4+3]) : "l"(x.y), "l"(w3.y));
            }
        }
        if (ch < 15) {
            ulonglong2* wn = wb + (1 - cur) * 1024;
#pragma unroll
            for (int c = 0; c < 4; c++)
                wn[c * 256 + tid] = make_ulonglong2(pw[2 * c], pw[2 * c + 1]);
        }
        __syncthreads();
    }
}

// ---------------- base = f @ Wf^T + pe @ Wq^T  (grid 512) ---------------------
__global__ void __launch_bounds__(256, 2) base_kernel(const float* __restrict__ f) {
    extern __shared__ float smem[];
    float* S = smem;
    ulonglong2* wb = (ulonglong2*)(smem + 32 * STR);
    int bid = blockIdx.x, tid = threadIdx.x;
    int b = bid >> 4, p = bid & 15, f0 = p * 32;
    size_t rb = ((size_t)b * Ff + f0) * Dd;

    ull acc[32];
#pragma unroll
    for (int i = 0; i < 32; i++) acc[i] = 0ULL;

#pragma unroll 4
    for (int r = 0; r < 32; r++) S[r * STR + tid] = g_pe[(f0 + r) * Dd + tid];
    gemm_tile(S, g_WqP, wb, acc, tid);      // internal sync covers S

#pragma unroll 4
    for (int r = 0; r < 32; r++) S[r * STR + tid] = f[rb + r * Dd + tid];
    gemm_tile(S, g_WfP, wb, acc, tid);

    int o0 = tid & 63, r0 = (tid >> 6) * 8;
#pragma unroll
    for (int i = 0; i < 8; i++)
#pragma unroll
        for (int j = 0; j < 4; j++)
            g_base[rb + (size_t)(r0 + i) * Dd + o0 + 64 * j] = red2(acc[i * 4 + j]);
}

// ---------------- fused LSTM step (grid 32, block 1024) -----------------------
__global__ void lstm_step_kernel(const int* __restrict__ ids,
                                 const float* __restrict__ emb, int t) {
    int b = blockIdx.x, tid = threadIdx.x;
    __shared__ __align__(16) float buf[768];
    __shared__ __align__(16) float hbuf[256];
    __shared__ float gsh[1024];
    if (tid < 256)      buf[tid] = emb[ids[b * Tt + t] * Dd + tid];
    else if (tid < 512) buf[tid] = g_cp[b * Dd + (tid - 256)];
    else if (tid < 768) buf[tid] = g_h[b * Dd + (tid - 512)];
    __syncthreads();
    ull acc = 0ULL;
#pragma unroll 8
    for (int jp = 0; jp < 384; jp++) {
        ull x = *(const ull*)(buf + 2 * jp);
        asm("fma.rn.f32x2 %0,%1,%2,%0;" : "+l"(acc) : "l"(x), "l"(g_wcombP[jp * 1024 + tid]));
    }
    gsh[tid] = red2(acc);
    __syncthreads();
    if (tid < 256) {
        float gi = gsh[tid], gf = gsh[256 + tid], gg = gsh[512 + tid], go = gsh[768 + tid];
        float c  = sigm(gf) * g_cell[b * Dd + tid] + sigm(gi) * tanhf(gg);
        float hn = sigm(go) * tanhf(c);
        g_cell[b * Dd + tid] = c;
        g_h[b * Dd + tid]    = hn;
        hbuf[tid] = hn;
    }
    __syncthreads();
    if (tid < 256) {
        ull a2 = 0ULL;
#pragma unroll 8
        for (int jp = 0; jp < 128; jp++) {
            ull x = *(const ull*)(hbuf + 2 * jp);
            asm("fma.rn.f32x2 %0,%1,%2,%0;" : "+l"(a2) : "l"(x), "l"(g_WhP[jp * 256 + tid]));
        }
        g_hw[b * Dd + tid] = red2(a2);
    }
}

// ---------------- fused attention step (grid 512) -----------------------------
__global__ void __launch_bounds__(256, 2) attn_kernel(const float* __restrict__ f) {
    extern __shared__ float smem[];
    float* S = smem;
    ulonglong2* wb = (ulonglong2*)(smem + 32 * STR);
    int bid = blockIdx.x, tid = threadIdx.x;
    int b = bid >> 4, p = bid & 15, f0 = p * 32;
    size_t rb = ((size_t)b * Ff + f0) * Dd;
    int o0 = tid & 63, r0 = (tid >> 6) * 8;

    // phase 1: X = tanh(hw + base + sW)
    {
        float hwv = g_hw[b * Dd + tid];
#pragma unroll 4
        for (int r = 0; r < 32; r++)
            S[r * STR + tid] = tanhf(hwv + g_base[rb + r * Dd + tid] + g_sW[rb + r * Dd + tid]);
    }

    // GEMM 1: E = X @ We^T
    ull acc[32];
#pragma unroll
    for (int i = 0; i < 32; i++) acc[i] = 0ULL;
    gemm_tile(S, g_WeP, wb, acc, tid);
#pragma unroll
    for (int i = 0; i < 8; i++)
#pragma unroll
        for (int j = 0; j < 4; j++)
            S[(r0 + i) * STR + o0 + 64 * j] = red2(acc[i * 4 + j]);
    __syncthreads();

    // softmax over 256 columns per row; warp w owns rows 4w..4w+3
    {
        int wi = tid >> 5, lane = tid & 31;
        for (int rr = 0; rr < 4; rr++) {
            int r = wi * 4 + rr;
            float v[8];
            float m = -1e30f;
#pragma unroll
            for (int k2 = 0; k2 < 8; k2++) { v[k2] = S[r * STR + lane + 32 * k2]; m = fmaxf(m, v[k2]); }
#pragma unroll
            for (int off = 16; off >= 1; off >>= 1) m = fmaxf(m, __shfl_xor_sync(0xffffffffu, m, off));
            float s = 0.0f;
#pragma unroll
            for (int k2 = 0; k2 < 8; k2++) { v[k2] = __expf(v[k2] - m); s += v[k2]; }
#pragma unroll
            for (int off = 16; off >= 1; off >>= 1) s += __shfl_xor_sync(0xffffffffu, s, off);
            float inv = 1.0f / s;
#pragma unroll
            for (int k2 = 0; k2 < 8; k2++) S[r * STR + lane + 32 * k2] = v[k2] * inv;
        }
    }
    __syncthreads();

    // c / cp partials (thread tid = column tid)
    {
        float cacc = 0.0f, cpacc = 0.0f;
#pragma unroll 4
        for (int r = 0; r < 32; r++) {
            float a  = S[r * STR + tid];
            float fv = f[rb + r * Dd + tid];
            cacc  += a * fv;
            cpacc += a * (fv + g_pe[(f0 + r) * Dd + tid]);
        }
        g_cpart[(p * Bb + b) * Dd + tid]  = cacc;
        g_cppart[(p * Bb + b) * Dd + tid] = cpacc;
    }
    __syncthreads();

    // GEMM 2: sW += alpha @ Ws^T
#pragma unroll
    for (int i = 0; i < 32; i++) acc[i] = 0ULL;
    gemm_tile(S, g_WsP, wb, acc, tid);
#pragma unroll
    for (int i = 0; i < 8; i++)
#pragma unroll
        for (int j = 0; j < 4; j++) {
            size_t gi = rb + (size_t)(r0 + i) * Dd + o0 + 64 * j;
            g_sW[gi] += red2(acc[i * 4 + j]);
        }
}

// ---------------- pred (grid 32) ----------------------------------------------
__global__ void pred_kernel(float* __restrict__ out, int t) {
    int b = blockIdx.x, tid = threadIdx.x;
    __shared__ __align__(16) float ch[512];
    float cs = 0.0f, cps = 0.0f;
#pragma unroll
    for (int p = 0; p < 16; p++) {
        cs  += g_cpart[(p * Bb + b) * Dd + tid];
        cps += g_cppart[(p * Bb + b) * Dd + tid];
    }
    g_cp[b * Dd + tid] = cps;
    ch[tid]       = cs;
    ch[256 + tid] = g_h[b * Dd + tid];
    __syncthreads();
    ull acc = 0ULL;
#pragma unroll 8
    for (int jp = 0; jp < 256; jp++) {
        ull x = *(const ull*)(ch + 2 * jp);
        asm("fma.rn.f32x2 %0,%1,%2,%0;" : "+l"(acc) : "l"(x), "l"(g_WgP[jp * 256 + tid]));
    }
    out[((size_t)b * Tt + t) * Dd + tid] = red2(acc);
}

// ---------------- launch ------------------------------------------------------

extern "C" void kernel_launch(void* const* d_in, const int* in_sizes, int n_in,
                              void* d_out, int out_size) {
    (void)in_sizes; (void)n_in; (void)out_size;
    const float* f    = (const float*)d_in[0];
    const int*   ids  = (const int*)d_in[1];
    const float* emb  = (const float*)d_in[2];
    const float* w_e  = (const float*)d_in[3];
    const float* w_h  = (const float*)d_in[4];
    const float* w_f  = (const float*)d_in[5];
    const float* w_q  = (const float*)d_in[6];
    const float* w_s  = (const float*)d_in[7];
    const float* w_g  = (const float*)d_in[8];
    const float* w_ih = (const float*)d_in[9];
    const float* w_hh = (const float*)d_in[10];
    float* out = (float*)d_out;

    const int SMEM_BYTES = 32 * STR * 4 + 2 * 1024 * 16;   // 33280 + 32768 = 66048
    cudaFuncSetAttribute(base_kernel, cudaFuncAttributeMaxDynamicSharedMemorySize, SMEM_BYTES);
    cudaFuncSetAttribute(attn_kernel, cudaFuncAttributeMaxDynamicSharedMemorySize, SMEM_BYTES);

    // launches (harness launches 2 kernels first; attn lands at global index 5 for ncu -s 5)
    setup_a<<<5088, 256>>>(w_f, w_q, w_h, w_ih, w_hh, w_g, w_e, w_s);   // my #0
    base_kernel<<<512, 256, SMEM_BYTES>>>(f);                            // my #1
    for (int t = 0; t < Tt; t++) {
        lstm_step_kernel<<<32, 1024>>>(ids, emb, t);                     // my #2 (t=0)
        attn_kernel<<<512, 256, SMEM_BYTES>>>(f);                        // my #3 (t=0) -> global #5
        pred_kernel<<<32, 256>>>(out, t);
    }
}